// round 16
// baseline (speedup 1.0000x reference)
#include <cuda_runtime.h>
#include <cuda_fp16.h>
#include <cstdint>
#include <cstddef>

#define T_STEPS 8192
#define I_DIM   64
#define H_DIM   2048
#define O_DIM   128
#define R4H     8192
#define G_CTA   148
#define NTH     480
#define NWARP   15
#define POLL_W  14
#define PADH    2560                 // 160 slots x 16 halfs (148 used)
#define ROWU4   (PADH / 8)           // 320 uint4 per padded weight row
// dyn smem: 42 weight rows (3/unit x 14 units) x 5120B + 5120B h buffer
#define SMEM_DYN_BYTES (42 * (PADH * 2) + PADH * 2)

// ---------------- device-global scratch (no runtime allocation) -------------
__device__ __half   g_w16[(size_t)R4H * PADH];      // 40 MB fp16 W_hh, unit-major rows, padded cols
__device__ float    g_xg[(size_t)T_STEPS * R4H];    // 256 MB x_gates [t][4*unit+gate]
__device__ __align__(16) __half g_hpad[2][PADH];    // double-buffered padded hidden
__device__ float    g_hT[H_DIM];                    // final h in fp32 (orig indexing)
__device__ unsigned g_arrive;
__device__ unsigned g_release;

__host__ __device__ __forceinline__ int ubeg(int c) {
    return (int)(((long long)c * H_DIM) / G_CTA);
}

__device__ __forceinline__ float tanh_fast(float x) {
    float r;
    asm("tanh.approx.f32 %0, %1;" : "=f"(r) : "f"(x));
    return r;
}
__device__ __forceinline__ float sig_fast(float x) {
    return fmaf(tanh_fast(0.5f * x), 0.5f, 0.5f);
}

// ---------------- init: reset cross-replay state -----------------------------
__global__ void init_k() {
    int i = blockIdx.x * blockDim.x + threadIdx.x;
    if (i < PADH) {
        g_hpad[0][i] = __float2half_rn(0.0f);
        g_hpad[1][i] = __float2half_rn(0.0f);
    }
    if (i == 0) { g_arrive = 0u; g_release = 0u; }
}

// ---------------- W_hh fp32 -> fp16, unit-major rows, padded columns --------
// orig row r = gate*2048 + unit -> prow = 4*unit + gate
// orig col k -> padded col 16*cta(k) + (k - u0(cta(k))); pad cols = 0
__global__ __launch_bounds__(256) void prep_w(const float* __restrict__ Whh) {
    int r = blockIdx.x;
    int prow = 4 * (r & (H_DIM - 1)) + (r >> 11);
    __half* dst = g_w16 + (size_t)prow * PADH;
    const float* src = Whh + (size_t)r * H_DIM;
    for (int p = threadIdx.x; p < PADH; p += 256) {
        int slot = p >> 4, pos = p & 15;
        float v = 0.0f;
        if (slot < G_CTA) {
            int u0s = ubeg(slot), nus = ubeg(slot + 1) - u0s;
            if (pos < nus) v = src[u0s + pos];
        }
        dst[p] = __float2half_rn(v);
    }
}

// ---------------- x_gates GEMM: g_xg[t][prow] = input[t]·W_ih[row] + biases --
__global__ __launch_bounds__(256) void xg_kernel(const float* __restrict__ inp,
                                                 const float* __restrict__ Wih,
                                                 const float* __restrict__ bih,
                                                 const float* __restrict__ bhh) {
    __shared__ float sI[64][64];
    __shared__ float sW[64][65];
    int t0b = blockIdx.x * 64;
    int r0b = blockIdx.y * 64;
    int tid = threadIdx.x;

    for (int i = tid; i < 64 * 16; i += 256) {
        int row = i >> 4, q = i & 15;
        float4 v = *(const float4*)(inp + (size_t)(t0b + row) * I_DIM + q * 4);
        *(float4*)(&sI[row][q * 4]) = v;
        float4 w = *(const float4*)(Wih + (size_t)(r0b + row) * I_DIM + q * 4);
        sW[row][q * 4 + 0] = w.x; sW[row][q * 4 + 1] = w.y;
        sW[row][q * 4 + 2] = w.z; sW[row][q * 4 + 3] = w.w;
    }
    __syncthreads();

    int tx = tid & 15, ty = tid >> 4;
    int rr = tx * 4, tt = ty * 4;
    float acc[4][4] = {};
#pragma unroll
    for (int k = 0; k < 64; k++) {
        float w0 = sW[rr + 0][k], w1 = sW[rr + 1][k];
        float w2 = sW[rr + 2][k], w3 = sW[rr + 3][k];
#pragma unroll
        for (int i = 0; i < 4; i++) {
            float x = sI[tt + i][k];
            acc[i][0] = fmaf(x, w0, acc[i][0]);
            acc[i][1] = fmaf(x, w1, acc[i][1]);
            acc[i][2] = fmaf(x, w2, acc[i][2]);
            acc[i][3] = fmaf(x, w3, acc[i][3]);
        }
    }
#pragma unroll
    for (int j = 0; j < 4; j++) {
        int r = r0b + rr + j;
        int prow = 4 * (r & (H_DIM - 1)) + (r >> 11);
        float b = bih[r] + bhh[r];
#pragma unroll
        for (int i = 0; i < 4; i++)
            g_xg[(size_t)(t0b + tt + i) * R4H + prow] = acc[i][j] + b;
    }
}

// ---------------- persistent recurrence kernel -------------------------------
__global__ void __launch_bounds__(NTH, 1) lstm_main(const float* __restrict__ Wlin,
                                                    const float* __restrict__ blin,
                                                    float* __restrict__ out) {
    extern __shared__ __align__(16) unsigned char smem_raw[];
    uint4* s_w = (uint4*)smem_raw;            // 42 rows x 320 uint4
    uint4* s_h = s_w + 42 * ROWU4;            // 320 uint4 padded h
    __shared__ __align__(16) __half s_hout[16];   // this CTA's h slot
    __shared__ unsigned s_flag;               // latest step whose h is in s_h
    __shared__ float    swr[NWARP];

    int cta  = blockIdx.x;
    int tid  = threadIdx.x;
    int wid  = tid >> 5;
    int lane = tid & 31;
    int u0 = ubeg(cta), nu = ubeg(cta + 1) - u0;   // 13 or 14

    if (tid == 0) s_flag = 0u;
    if (tid < 16) s_hout[tid] = __float2half_rn(0.0f);
    for (int i = tid; i < ROWU4; i += NTH)
        s_h[i] = make_uint4(0u, 0u, 0u, 0u);   // h(0) = 0 (padded)

    // per-warp weight staging: rows 0..2 of owned unit -> SMEM, row 3 -> regs
    uint4 wreg[10];
    int ugl = u0 + wid;
    if (wid < nu) {
        const uint4* wsrc = ((const uint4*)g_w16) + (size_t)(4 * ugl) * ROWU4;
#pragma unroll
        for (int j = 0; j < 3; j++) {
            uint4* dst = s_w + (size_t)(3 * wid + j) * ROWU4;
            for (int k = 0; k < 10; k++)
                dst[k * 32 + lane] = __ldg(wsrc + (size_t)j * ROWU4 + k * 32 + lane);
        }
#pragma unroll
        for (int k = 0; k < 10; k++)
            wreg[k] = __ldg(wsrc + (size_t)3 * ROWU4 + k * 32 + lane);
    }
    __syncthreads();

    if (wid == POLL_W) {
        // ---- poller warp: spin on release, vector-copy padded h into SMEM --
        for (unsigned t = 1; t <= (unsigned)T_STEPS; t++) {
            unsigned v;
            do {
                asm volatile("ld.acquire.gpu.global.u32 %0, [%1];"
                             : "=r"(v) : "l"(&g_release) : "memory");
            } while (v < t);
            const uint4* src = (const uint4*)(g_hpad[t & 1]);
            uint4 a[10];
#pragma unroll
            for (int k = 0; k < 10; k++) a[k] = __ldcg(src + k * 32 + lane);
#pragma unroll
            for (int k = 0; k < 10; k++) s_h[k * 32 + lane] = a[k];
            asm volatile("bar.sync 1, 32;" ::: "memory");   // drain STS
            if (lane == 0)
                asm volatile("st.release.cta.u32 [%0], %1;"
                             :: "l"(&s_flag), "r"(t) : "memory");
        }
    } else if (wid < nu) {
        // ---- dot warp: owns hidden unit ugl; 3 SMEM rows + 1 register row --
        const uint4* wrow0 = s_w + (size_t)(3 * wid) * ROWU4;
        unsigned barcnt = (unsigned)(nu * 32);
        float c_val = 0.0f;

        for (int t = 0; t < T_STEPS; t++) {
            float4 xgv = make_float4(0.f, 0.f, 0.f, 0.f);
            if (lane == 0)
                xgv = *(const float4*)(g_xg + (size_t)t * R4H + 4 * ugl);

            unsigned f;
            do {
                asm volatile("ld.acquire.cta.u32 %0, [%1];"
                             : "=r"(f) : "l"(&s_flag) : "memory");
            } while (f < (unsigned)t);

            __half2 a0[4], a1[4];
#pragma unroll
            for (int j = 0; j < 4; j++) {
                a0[j] = __float2half2_rn(0.0f);
                a1[j] = __float2half2_rn(0.0f);
            }
#pragma unroll
            for (int half = 0; half < 2; half++) {
                uint4 hv[5];
#pragma unroll
                for (int k = 0; k < 5; k++)
                    hv[k] = s_h[(half * 5 + k) * 32 + lane];
#pragma unroll
                for (int j = 0; j < 3; j++) {
                    const uint4* wr = wrow0 + (size_t)j * ROWU4;
#pragma unroll
                    for (int k = 0; k < 5; k++) {
                        uint4 w = wr[(half * 5 + k) * 32 + lane];
                        a0[j] = __hfma2(*(const __half2*)&w.x, *(const __half2*)&hv[k].x, a0[j]);
                        a1[j] = __hfma2(*(const __half2*)&w.y, *(const __half2*)&hv[k].y, a1[j]);
                        a0[j] = __hfma2(*(const __half2*)&w.z, *(const __half2*)&hv[k].z, a0[j]);
                        a1[j] = __hfma2(*(const __half2*)&w.w, *(const __half2*)&hv[k].w, a1[j]);
                    }
                }
#pragma unroll
                for (int k = 0; k < 5; k++) {
                    uint4 w = wreg[half * 5 + k];
                    a0[3] = __hfma2(*(const __half2*)&w.x, *(const __half2*)&hv[k].x, a0[3]);
                    a1[3] = __hfma2(*(const __half2*)&w.y, *(const __half2*)&hv[k].y, a1[3]);
                    a0[3] = __hfma2(*(const __half2*)&w.z, *(const __half2*)&hv[k].z, a0[3]);
                    a1[3] = __hfma2(*(const __half2*)&w.w, *(const __half2*)&hv[k].w, a1[3]);
                }
            }
            float s[4];
#pragma unroll
            for (int j = 0; j < 4; j++) {
                float2 f0 = __half22float2(a0[j]);
                float2 f1 = __half22float2(a1[j]);
                s[j] = (f0.x + f0.y) + (f1.x + f1.y);
            }
#pragma unroll
            for (int sh = 16; sh > 0; sh >>= 1) {
                s[0] += __shfl_xor_sync(0xffffffffu, s[0], sh);
                s[1] += __shfl_xor_sync(0xffffffffu, s[1], sh);
                s[2] += __shfl_xor_sync(0xffffffffu, s[2], sh);
                s[3] += __shfl_xor_sync(0xffffffffu, s[3], sh);
            }

            if (lane == 0) {
                float xi = s[0] + xgv.x;
                float xf = s[1] + xgv.y;
                float xg = s[2] + xgv.z;
                float xo = s[3] + xgv.w;
                float ig = sig_fast(xi);
                float fg = sig_fast(xf);
                float gg = tanh_fast(xg);
                float og = sig_fast(xo);
                c_val = fg * c_val + ig * gg;
                float h = og * tanh_fast(c_val);
                s_hout[wid] = __float2half_rn(h);
                if (t == T_STEPS - 1) {
                    g_hT[ugl] = h;
                    __threadfence();      // one-time: order g_hT before arrive chain
                }
            }
            __syncwarp();

            if (wid == 0) {
                // collect all units (BAR drains the owners' STS), publish slot
                asm volatile("bar.sync 2, %0;" :: "r"(barcnt) : "memory");
                if (lane == 0) {
                    uint4 p0 = *(const uint4*)(s_hout);
                    uint4 p1 = *(const uint4*)(s_hout + 8);
                    uint4* slot = ((uint4*)(g_hpad[(t & 1) ^ 1])) + 2 * cta;
                    slot[0] = p0;
                    slot[1] = p1;
                    __threadfence();      // 2 stores -> gpu-visible
                    unsigned pg;
                    asm volatile("atom.acq_rel.gpu.global.add.u32 %0, [%1], %2;"
                                 : "=r"(pg) : "l"(&g_arrive), "r"(1u) : "memory");
                    if (pg + 1u == (unsigned)(t + 1) * (unsigned)G_CTA) {
                        asm volatile("st.release.gpu.global.u32 [%0], %1;"
                                     :: "l"(&g_release), "r"((unsigned)(t + 1)) : "memory");
                    }
                }
            } else {
                asm volatile("bar.arrive 2, %0;" :: "r"(barcnt) : "memory");
            }
        }
    }
    // idle warp (wid in [nu, POLL_W)) falls straight through

    __syncthreads();   // poller exits only after release(T_STEPS) observed

    // ---- final linear: CTA o (< 128) computes out[o] = h_T · W_lin[o] + b ----
    if (cta < O_DIM) {
        const float* wrow = Wlin + (size_t)cta * H_DIM;
        float s = 0.0f;
        for (int k = tid; k < H_DIM; k += NTH)
            s = fmaf(__ldcg(g_hT + k), __ldg(wrow + k), s);
#pragma unroll
        for (int sh = 16; sh > 0; sh >>= 1)
            s += __shfl_xor_sync(0xffffffffu, s, sh);
        if (lane == 0) swr[wid] = s;
        __syncthreads();
        if (tid == 0) {
            float tot = 0.0f;
#pragma unroll
            for (int w = 0; w < NWARP; w++) tot += swr[w];
            out[cta] = tot + __ldg(blin + cta);
        }
    }
}

// ---------------- launch ------------------------------------------------------
extern "C" void kernel_launch(void* const* d_in, const int* in_sizes, int n_in,
                              void* d_out, int out_size) {
    const float* inp  = (const float*)d_in[0];
    const float* Wih  = (const float*)d_in[1];
    const float* Whh  = (const float*)d_in[2];
    const float* bih  = (const float*)d_in[3];
    const float* bhh  = (const float*)d_in[4];
    const float* Wlin = (const float*)d_in[5];
    const float* blin = (const float*)d_in[6];
    float* out = (float*)d_out;
    (void)in_sizes; (void)n_in; (void)out_size;

    cudaFuncSetAttribute(lstm_main, cudaFuncAttributeMaxDynamicSharedMemorySize,
                         SMEM_DYN_BYTES);

    init_k<<<(PADH + 255) / 256, 256>>>();
    prep_w<<<R4H, 256>>>(Whh);
    dim3 gx(T_STEPS / 64, R4H / 64);
    xg_kernel<<<gx, 256>>>(inp, Wih, bih, bhh);
    lstm_main<<<G_CTA, NTH, SMEM_DYN_BYTES>>>(Wlin, blin, out);
}